// round 8
// baseline (speedup 1.0000x reference)
#include <cuda_runtime.h>
#include <math.h>

#define NDOC 4096
#define VW   10000
#define KTOP 100
#define EDIM 384

// ---------------- device state (static scratch; allocation-free) -------------
__device__ float g_Mdt[NDOC*KTOP];
__device__ float g_Kdt[NDOC*KTOP];
__device__ float g_KdtT[KTOP*NDOC];
__device__ float g_Mtw[KTOP*VW];
__device__ float g_Ktw[KTOP*VW];
__device__ float g_KtwT[VW*KTOP];
__device__ float g_theta[NDOC*KTOP];
__device__ float g_beta[KTOP*VW];
__device__ float g_u1[NDOC], g_v1[KTOP], g_v1fin[KTOP], g_b1[KTOP];
__device__ float g_u2[KTOP], g_v2[VW],  g_v2fin[VW],  g_b2[VW];
__device__ float g_nd[NDOC], g_nt[KTOP], g_nw[VW];
__device__ float g_errpart[256];
__device__ double g_acc[3];          // [0]=loss_DT  [1]=loss_TW  [2]=sum bow*log(recon)
__device__ unsigned g_barcnt;
__device__ volatile unsigned g_bargen;

// ---------------- helpers ----------------------------------------------------
__device__ __forceinline__ float warp_sum(float v){
    v += __shfl_down_sync(0xffffffffu, v, 16);
    v += __shfl_down_sync(0xffffffffu, v, 8);
    v += __shfl_down_sync(0xffffffffu, v, 4);
    v += __shfl_down_sync(0xffffffffu, v, 2);
    v += __shfl_down_sync(0xffffffffu, v, 1);
    return v;
}

// sense-reversing software grid barrier (all CTAs co-resident: grid = 148 <= #SMs)
__device__ __forceinline__ void gridbar(){
    __syncthreads();
    if (threadIdx.x == 0){
        __threadfence();
        unsigned g  = g_bargen;
        unsigned nb = gridDim.x;
        if (atomicAdd(&g_barcnt, 1u) == nb - 1u){
            g_barcnt = 0u;
            __threadfence();
            g_bargen = g + 1u;
        } else {
            while (g_bargen == g) { __nanosleep(64); }
            __threadfence();
        }
    }
    __syncthreads();
}

// ---------------- setup kernels ----------------------------------------------
__global__ void init_kernel(){
    if (threadIdx.x == 0){
        g_barcnt = 0u; g_bargen = 0u;
        g_acc[0] = 0.0; g_acc[1] = 0.0; g_acc[2] = 0.0;
    }
}

// row squared-norms; sel: 0=doc->g_nd, 1=topic->g_nt, 2=word->g_nw
__global__ void norms_kernel(const float* __restrict__ x, int n, int sel){
    float* out = (sel == 0) ? g_nd : ((sel == 1) ? g_nt : g_nw);
    int gt = blockIdx.x * blockDim.x + threadIdx.x;
    int gw = gt >> 5, lane = threadIdx.x & 31;
    int nw = (gridDim.x * blockDim.x) >> 5;
    for (int i = gw; i < n; i += nw){
        const float* row = x + (size_t)i * EDIM;
        float s = 0.f;
        for (int e = lane; e < EDIM; e += 32){ float t = row[e]; s += t * t; }
        s = warp_sum(s);
        if (lane == 0) out[i] = s;
    }
}

// softmax; sel: 0 -> g_b1 (topic weights, n=100), 1 -> g_b2 (word weights, n=10000)
__global__ void softmax_kernel(const float* __restrict__ x, int n, int sel){
    float* out = (sel == 0) ? g_b1 : g_b2;
    __shared__ float red[1024];
    int tid = threadIdx.x, nt = blockDim.x;
    float m = -3.4e38f;
    for (int i = tid; i < n; i += nt) m = fmaxf(m, x[i]);
    red[tid] = m; __syncthreads();
    for (int s = nt >> 1; s > 0; s >>= 1){ if (tid < s) red[tid] = fmaxf(red[tid], red[tid+s]); __syncthreads(); }
    m = red[0]; __syncthreads();
    float sum = 0.f;
    for (int i = tid; i < n; i += nt) sum += expf(x[i] - m);
    red[tid] = sum; __syncthreads();
    for (int s = nt >> 1; s > 0; s >>= 1){ if (tid < s) red[tid] += red[tid+s]; __syncthreads(); }
    sum = red[0]; __syncthreads();
    float inv = 1.0f / sum;
    for (int i = tid; i < n; i += nt) out[i] = expf(x[i] - m) * inv;
}

// pairwise sq-euclidean + K=exp(-alpha*M) + transpose copy.
// which: 0 = DT (doc x topic), 1 = TW (topic x word)
__global__ __launch_bounds__(256) void dist_kernel(
    const float* __restrict__ A, const float* __restrict__ B,
    int nA, int nB, float alpha, int which)
{
    float* Mout  = which ? g_Mtw  : g_Mdt;
    float* Kout  = which ? g_Ktw  : g_Kdt;
    float* KTout = which ? g_KtwT : g_KdtT;
    const float* nAarr = which ? g_nt : g_nd;
    const float* nBarr = which ? g_nw : g_nt;

    __shared__ float As[64*33];
    __shared__ float Bs[64*33];
    int tid = threadIdx.x;
    int tx = tid & 15, ty = tid >> 4;
    int r0 = blockIdx.y * 64, c0 = blockIdx.x * 64;

    float acc[4][4];
#pragma unroll
    for (int i = 0; i < 4; i++)
#pragma unroll
        for (int j = 0; j < 4; j++) acc[i][j] = 0.f;

    for (int ec = 0; ec < EDIM; ec += 32){
        __syncthreads();
        for (int f = tid; f < 64*32; f += 256){
            int r = f >> 5, c = f & 31;
            As[r*33 + c] = (r0 + r < nA) ? A[(size_t)(r0 + r)*EDIM + ec + c] : 0.f;
            Bs[r*33 + c] = (c0 + r < nB) ? B[(size_t)(c0 + r)*EDIM + ec + c] : 0.f;
        }
        __syncthreads();
#pragma unroll
        for (int e = 0; e < 32; e++){
            float a[4], b[4];
#pragma unroll
            for (int i = 0; i < 4; i++) a[i] = As[(i*16 + ty)*33 + e];
#pragma unroll
            for (int j = 0; j < 4; j++) b[j] = Bs[(j*16 + tx)*33 + e];
#pragma unroll
            for (int i = 0; i < 4; i++)
#pragma unroll
                for (int j = 0; j < 4; j++) acc[i][j] = fmaf(a[i], b[j], acc[i][j]);
        }
    }
#pragma unroll
    for (int i = 0; i < 4; i++){
        int r = r0 + i*16 + ty;
        if (r >= nA) continue;
#pragma unroll
        for (int j = 0; j < 4; j++){
            int c = c0 + j*16 + tx;
            if (c >= nB) continue;
            float M = nAarr[r] + nBarr[c] - 2.0f * acc[i][j];
            Mout[(size_t)r*nB + c] = M;
            float kv = expf(-alpha * M);
            Kout[(size_t)r*nB + c] = kv;
            KTout[(size_t)c*nA + r] = kv;
        }
    }
}

// ---------------- persistent Sinkhorn kernels --------------------------------
// DT: rows NDOC, cols KTOP. u-phase warp-per-row, s/v-phase block-per-column.
__global__ __launch_bounds__(256) void sink_dt_kernel(){
    __shared__ float red[256];
    __shared__ float sh_err;
    int tid = threadIdx.x, bid = blockIdx.x, nb = gridDim.x;
    int gt = bid*256 + tid;
    int gw = gt >> 5, lane = tid & 31;
    int nwarps = (nb * 256) >> 5;
    const float inv_n = 1.0f / (float)NDOC;

    for (int i = gt; i < NDOC; i += nb*256) g_u1[i] = inv_n;
    gridbar();

    // init: v1 = b1 / (K^T u0 + eps)
    {
        float t = 0.f;
        if (bid < KTOP){
            const float* col = g_KdtT + (size_t)bid * NDOC;
            for (int i = tid; i < NDOC; i += 256) t += col[i] * g_u1[i];
        }
        red[tid] = t; __syncthreads();
        for (int s = 128; s > 0; s >>= 1){ if (tid < s) red[tid] += red[tid+s]; __syncthreads(); }
        if (tid == 0 && bid < KTOP) g_v1[bid] = g_b1[bid] / (red[0] + 1e-16f);
        __syncthreads();
    }
    gridbar();

    float err = 1.0f; int cpt = 0;
    while (err > 0.005f && cpt < 5000){
        // u = a / (K v + eps)   (warp per row)
        for (int i = gw; i < NDOC; i += nwarps){
            const float* row = g_Kdt + (size_t)i * KTOP;
            float t = 0.f;
            for (int j = lane; j < KTOP; j += 32) t += row[j] * g_v1[j];
            t = warp_sum(t);
            if (lane == 0) g_u1[i] = inv_n / (t + 1e-16f);
        }
        gridbar();
        cpt++;
        bool check = (cpt % 50) == 1;
        // s = K^T u ; err uses old v ; v <- b/(s+eps)   (block per column)
        {
            float t = 0.f;
            if (bid < KTOP){
                const float* col = g_KdtT + (size_t)bid * NDOC;
                for (int i = tid; i < NDOC; i += 256) t += col[i] * g_u1[i];
            }
            red[tid] = t; __syncthreads();
            for (int s = 128; s > 0; s >>= 1){ if (tid < s) red[tid] += red[tid+s]; __syncthreads(); }
            if (tid == 0){
                float ep = 0.f;
                if (bid < KTOP){
                    float s = red[0];
                    float vold = g_v1[bid];
                    g_v1fin[bid] = vold;
                    if (check) ep = fabsf(vold * s - g_b1[bid]);
                    g_v1[bid] = g_b1[bid] / (s + 1e-16f);
                }
                if (check) g_errpart[bid] = ep;
            }
            __syncthreads();
        }
        gridbar();
        if (check){
            if (tid == 0){
                float e = 0.f;
                for (int b = 0; b < nb; b++) e += g_errpart[b];
                sh_err = e;
            }
            __syncthreads();
            err = sh_err;
        }
    }
}

// TW: rows KTOP, cols VW. u-phase block-per-row, s/v-phase warp-per-column.
__global__ __launch_bounds__(256) void sink_tw_kernel(){
    __shared__ float red[256];
    __shared__ float sh_err;
    int tid = threadIdx.x, bid = blockIdx.x, nb = gridDim.x;
    int gt = bid*256 + tid;
    int gw = gt >> 5, lane = tid & 31;
    int nwarps = (nb * 256) >> 5;
    const float inv_n = 1.0f / (float)KTOP;

    for (int i = gt; i < KTOP; i += nb*256) g_u2[i] = inv_n;
    gridbar();

    // init v2
    for (int j = gw; j < VW; j += nwarps){
        const float* col = g_KtwT + (size_t)j * KTOP;
        float t = 0.f;
        for (int i = lane; i < KTOP; i += 32) t += col[i] * g_u2[i];
        t = warp_sum(t);
        if (lane == 0) g_v2[j] = g_b2[j] / (t + 1e-16f);
    }
    gridbar();

    float err = 1.0f; int cpt = 0;
    while (err > 0.005f && cpt < 5000){
        // u = a/(K v + eps)  (block per row)
        {
            float t = 0.f;
            if (bid < KTOP){
                const float* row = g_Ktw + (size_t)bid * VW;
                for (int j = tid; j < VW; j += 256) t += row[j] * g_v2[j];
            }
            red[tid] = t; __syncthreads();
            for (int s = 128; s > 0; s >>= 1){ if (tid < s) red[tid] += red[tid+s]; __syncthreads(); }
            if (tid == 0 && bid < KTOP) g_u2[bid] = inv_n / (red[0] + 1e-16f);
            __syncthreads();
        }
        gridbar();
        cpt++;
        bool check = (cpt % 50) == 1;
        // s = K^T u ; err ; v update (warp per column)
        {
            float ep = 0.f;
            for (int j = gw; j < VW; j += nwarps){
                const float* col = g_KtwT + (size_t)j * KTOP;
                float t = 0.f;
                for (int i = lane; i < KTOP; i += 32) t += col[i] * g_u2[i];
                t = warp_sum(t);
                if (lane == 0){
                    float vold = g_v2[j];
                    g_v2fin[j] = vold;
                    if (check) ep += fabsf(vold * t - g_b2[j]);
                    g_v2[j] = g_b2[j] / (t + 1e-16f);
                }
            }
            if (check){
                red[tid] = ep; __syncthreads();
                for (int s = 128; s > 0; s >>= 1){ if (tid < s) red[tid] += red[tid+s]; __syncthreads(); }
                if (tid == 0) g_errpart[bid] = red[0];
                __syncthreads();
            }
        }
        gridbar();
        if (check){
            if (tid == 0){
                float e = 0.f;
                for (int b = 0; b < nb; b++) e += g_errpart[b];
                sh_err = e;
            }
            __syncthreads();
            err = sh_err;
        }
    }
}

// ---------------- transport matrices + transport losses ----------------------
__global__ __launch_bounds__(256) void theta_kernel(){
    __shared__ float red[256];
    int tid = threadIdx.x;
    int g = blockIdx.x*256 + tid, stride = gridDim.x*256;
    float part = 0.f;
    for (int idx = g; idx < NDOC*KTOP; idx += stride){
        int i = idx / KTOP, k = idx - i*KTOP;
        float tr = g_u1[i] * g_Kdt[idx] * g_v1fin[k];
        g_theta[idx] = tr * (float)NDOC;
        part += tr * g_Mdt[idx];
    }
    red[tid] = part; __syncthreads();
    for (int s = 128; s > 0; s >>= 1){ if (tid < s) red[tid] += red[tid+s]; __syncthreads(); }
    if (tid == 0) atomicAdd(&g_acc[0], (double)red[0]);
}

__global__ __launch_bounds__(256) void beta_kernel(){
    __shared__ float red[256];
    int tid = threadIdx.x;
    int g = blockIdx.x*256 + tid, stride = gridDim.x*256;
    float part = 0.f;
    for (int idx = g; idx < KTOP*VW; idx += stride){
        int k = idx / VW, j = idx - k*VW;
        float tr = g_u2[k] * g_Ktw[idx] * g_v2fin[j];
        g_beta[idx] = tr * (float)KTOP;
        part += tr * g_Mtw[idx];
    }
    red[tid] = part; __syncthreads();
    for (int s = 128; s > 0; s >>= 1){ if (tid < s) red[tid] += red[tid+s]; __syncthreads(); }
    if (tid == 0) atomicAdd(&g_acc[1], (double)red[0]);
}

// ---------------- fused recon GEMM + log-loss --------------------------------
// tile: 128 rows x 80 cols, 256 threads (16x16), 8x5 per thread, K-chunks of 25
__global__ __launch_bounds__(256) void recon_kernel(const float* __restrict__ bow){
    __shared__ float As[128*25];
    __shared__ float Bs[25*80];
    __shared__ float red[256];
    int tid = threadIdx.x;
    int tx = tid & 15, ty = tid >> 4;
    int r0 = blockIdx.y * 128;
    int c0 = blockIdx.x * 80;

    float acc[8][5];
#pragma unroll
    for (int i = 0; i < 8; i++)
#pragma unroll
        for (int j = 0; j < 5; j++) acc[i][j] = 0.f;

    for (int kc = 0; kc < 100; kc += 25){
        __syncthreads();
        for (int f = tid; f < 128*25; f += 256){
            int r = f / 25, c = f - r*25;
            As[f] = g_theta[(size_t)(r0 + r)*KTOP + kc + c];
        }
        for (int f = tid; f < 25*80; f += 256){
            int r = f / 80, c = f - r*80;
            Bs[f] = g_beta[(size_t)(kc + r)*VW + c0 + c];
        }
        __syncthreads();
#pragma unroll
        for (int k = 0; k < 25; k++){
            float a[8], b[5];
#pragma unroll
            for (int i = 0; i < 8; i++) a[i] = As[(i*16 + ty)*25 + k];
#pragma unroll
            for (int j = 0; j < 5; j++) b[j] = Bs[k*80 + (j*16 + tx)];
#pragma unroll
            for (int i = 0; i < 8; i++)
#pragma unroll
                for (int j = 0; j < 5; j++) acc[i][j] = fmaf(a[i], b[j], acc[i][j]);
        }
    }

    float part = 0.f;
#pragma unroll
    for (int i = 0; i < 8; i++){
        int r = r0 + i*16 + ty;
        const float* brow = bow + (size_t)r*VW + c0;
#pragma unroll
        for (int j = 0; j < 5; j++){
            part += brow[j*16 + tx] * __logf(acc[i][j] + 1e-12f);
        }
    }
    red[tid] = part; __syncthreads();
    for (int s = 128; s > 0; s >>= 1){ if (tid < s) red[tid] += red[tid+s]; __syncthreads(); }
    if (tid == 0) atomicAdd(&g_acc[2], (double)red[0]);
}

__global__ void final_kernel(float* out){
    out[0] = (float)(g_acc[0] + g_acc[1] - g_acc[2] * (1.0 / (double)NDOC));
}

// ---------------- launch -----------------------------------------------------
extern "C" void kernel_launch(void* const* d_in, const int* in_sizes, int n_in,
                              void* d_out, int out_size)
{
    const float *bow = nullptr, *doc = nullptr, *word = nullptr,
                *topic = nullptr, *ww = nullptr, *tw = nullptr;
    for (int i = 0; i < n_in; i++){
        const float* p = (const float*)d_in[i];
        switch (in_sizes[i]){
            case 40960000: bow = p;   break;   // train_bow [4096,10000]
            case 1572864:  doc = p;   break;   // doc_embeddings [4096,384]
            case 3840000:  word = p;  break;   // word_embeddings [10000,384]
            case 38400:    topic = p; break;   // topic_embeddings [100,384]
            case 10000:    ww = p;    break;   // word_weights
            case 100:      tw = p;    break;   // topic_weights
        }
    }
    float* out = (float*)d_out;

    init_kernel<<<1, 32>>>();

    norms_kernel<<<256, 256>>>(doc,   NDOC, 0);
    norms_kernel<<<16,  256>>>(topic, KTOP, 1);
    norms_kernel<<<256, 256>>>(word,  VW,   2);

    softmax_kernel<<<1, 1024>>>(tw, KTOP, 0);
    softmax_kernel<<<1, 1024>>>(ww, VW,   1);

    // DT distances: doc(4096) x topic(100)
    dist_kernel<<<dim3(2, 64), 256>>>(doc, topic, NDOC, KTOP, 3.0f, 0);
    // TW distances: topic(100) x word(10000)
    dist_kernel<<<dim3(157, 2), 256>>>(topic, word, KTOP, VW, 2.0f, 1);

    sink_dt_kernel<<<148, 256>>>();
    sink_tw_kernel<<<148, 256>>>();

    theta_kernel<<<320, 256>>>();
    beta_kernel<<<512, 256>>>();

    recon_kernel<<<dim3(125, 32), 256>>>(bow);

    final_kernel<<<1, 1>>>(out);
}

// round 9
// speedup vs baseline: 1.0087x; 1.0087x over previous
#include <cuda_runtime.h>
#include <math.h>

#define NDOC 4096
#define VW   10000
#define KTOP 100
#define EDIM 384

// ---------------- device state (static scratch; allocation-free) -------------
__device__ float g_Mdt[NDOC*KTOP];
__device__ float g_Kdt[NDOC*KTOP];
__device__ float g_KdtT[KTOP*NDOC];
__device__ float g_Mtw[KTOP*VW];
__device__ float g_Ktw[KTOP*VW];
__device__ float g_KtwT[VW*KTOP];
__device__ float g_theta[NDOC*KTOP];
__device__ float g_beta[KTOP*VW];
__device__ float g_u1[NDOC], g_v1[KTOP], g_v1fin[KTOP], g_b1[KTOP];
__device__ float g_u2[KTOP], g_v2[VW],  g_v2fin[VW],  g_b2[VW];
__device__ float g_nd[NDOC], g_nt[KTOP], g_nw[VW];
__device__ float g_errpart[256];
__device__ double g_acc[3];          // [0]=loss_DT  [1]=loss_TW  [2]=sum bow*log(recon)
__device__ unsigned g_barcnt;
__device__ volatile unsigned g_bargen;

// ---------------- helpers ----------------------------------------------------
__device__ __forceinline__ float warp_sum(float v){
    v += __shfl_down_sync(0xffffffffu, v, 16);
    v += __shfl_down_sync(0xffffffffu, v, 8);
    v += __shfl_down_sync(0xffffffffu, v, 4);
    v += __shfl_down_sync(0xffffffffu, v, 2);
    v += __shfl_down_sync(0xffffffffu, v, 1);
    return v;
}

// sense-reversing software grid barrier (all CTAs co-resident: grid = 148 <= #SMs)
__device__ __forceinline__ void gridbar(){
    __syncthreads();
    if (threadIdx.x == 0){
        __threadfence();
        unsigned g  = g_bargen;
        unsigned nb = gridDim.x;
        if (atomicAdd(&g_barcnt, 1u) == nb - 1u){
            g_barcnt = 0u;
            __threadfence();
            g_bargen = g + 1u;
        } else {
            while (g_bargen == g) { __nanosleep(64); }
            __threadfence();
        }
    }
    __syncthreads();
}

// ---------------- setup kernels ----------------------------------------------
__global__ void init_kernel(){
    if (threadIdx.x == 0){
        g_barcnt = 0u; g_bargen = 0u;
        g_acc[0] = 0.0; g_acc[1] = 0.0; g_acc[2] = 0.0;
    }
}

// row squared-norms; sel: 0=doc->g_nd, 1=topic->g_nt, 2=word->g_nw
__global__ void norms_kernel(const float* __restrict__ x, int n, int sel){
    float* out = (sel == 0) ? g_nd : ((sel == 1) ? g_nt : g_nw);
    int gt = blockIdx.x * blockDim.x + threadIdx.x;
    int gw = gt >> 5, lane = threadIdx.x & 31;
    int nw = (gridDim.x * blockDim.x) >> 5;
    for (int i = gw; i < n; i += nw){
        const float* row = x + (size_t)i * EDIM;
        float s = 0.f;
        for (int e = lane; e < EDIM; e += 32){ float t = row[e]; s += t * t; }
        s = warp_sum(s);
        if (lane == 0) out[i] = s;
    }
}

// softmax; sel: 0 -> g_b1 (topic weights, n=100), 1 -> g_b2 (word weights, n=10000)
__global__ void softmax_kernel(const float* __restrict__ x, int n, int sel){
    float* out = (sel == 0) ? g_b1 : g_b2;
    __shared__ float red[1024];
    int tid = threadIdx.x, nt = blockDim.x;
    float m = -3.4e38f;
    for (int i = tid; i < n; i += nt) m = fmaxf(m, x[i]);
    red[tid] = m; __syncthreads();
    for (int s = nt >> 1; s > 0; s >>= 1){ if (tid < s) red[tid] = fmaxf(red[tid], red[tid+s]); __syncthreads(); }
    m = red[0]; __syncthreads();
    float sum = 0.f;
    for (int i = tid; i < n; i += nt) sum += expf(x[i] - m);
    red[tid] = sum; __syncthreads();
    for (int s = nt >> 1; s > 0; s >>= 1){ if (tid < s) red[tid] += red[tid+s]; __syncthreads(); }
    sum = red[0]; __syncthreads();
    float inv = 1.0f / sum;
    for (int i = tid; i < n; i += nt) out[i] = expf(x[i] - m) * inv;
}

// pairwise sq-euclidean + K=exp(-alpha*M) + transpose copy.
// which: 0 = DT (doc x topic), 1 = TW (topic x word)
__global__ __launch_bounds__(256) void dist_kernel(
    const float* __restrict__ A, const float* __restrict__ B,
    int nA, int nB, float alpha, int which)
{
    float* Mout  = which ? g_Mtw  : g_Mdt;
    float* Kout  = which ? g_Ktw  : g_Kdt;
    float* KTout = which ? g_KtwT : g_KdtT;
    const float* nAarr = which ? g_nt : g_nd;
    const float* nBarr = which ? g_nw : g_nt;

    __shared__ float As[64*33];
    __shared__ float Bs[64*33];
    int tid = threadIdx.x;
    int tx = tid & 15, ty = tid >> 4;
    int r0 = blockIdx.y * 64, c0 = blockIdx.x * 64;

    float acc[4][4];
#pragma unroll
    for (int i = 0; i < 4; i++)
#pragma unroll
        for (int j = 0; j < 4; j++) acc[i][j] = 0.f;

    for (int ec = 0; ec < EDIM; ec += 32){
        __syncthreads();
        for (int f = tid; f < 64*32; f += 256){
            int r = f >> 5, c = f & 31;
            As[r*33 + c] = (r0 + r < nA) ? A[(size_t)(r0 + r)*EDIM + ec + c] : 0.f;
            Bs[r*33 + c] = (c0 + r < nB) ? B[(size_t)(c0 + r)*EDIM + ec + c] : 0.f;
        }
        __syncthreads();
#pragma unroll
        for (int e = 0; e < 32; e++){
            float a[4], b[4];
#pragma unroll
            for (int i = 0; i < 4; i++) a[i] = As[(i*16 + ty)*33 + e];
#pragma unroll
            for (int j = 0; j < 4; j++) b[j] = Bs[(j*16 + tx)*33 + e];
#pragma unroll
            for (int i = 0; i < 4; i++)
#pragma unroll
                for (int j = 0; j < 4; j++) acc[i][j] = fmaf(a[i], b[j], acc[i][j]);
        }
    }
#pragma unroll
    for (int i = 0; i < 4; i++){
        int r = r0 + i*16 + ty;
        if (r >= nA) continue;
#pragma unroll
        for (int j = 0; j < 4; j++){
            int c = c0 + j*16 + tx;
            if (c >= nB) continue;
            float M = nAarr[r] + nBarr[c] - 2.0f * acc[i][j];
            Mout[(size_t)r*nB + c] = M;
            float kv = expf(-alpha * M);
            Kout[(size_t)r*nB + c] = kv;
            KTout[(size_t)c*nA + r] = kv;
        }
    }
}

// ---------------- persistent Sinkhorn kernels --------------------------------
// DT: rows NDOC, cols KTOP. u-phase warp-per-row, s/v-phase block-per-column.
__global__ __launch_bounds__(256) void sink_dt_kernel(){
    __shared__ float red[256];
    __shared__ float sh_err;
    int tid = threadIdx.x, bid = blockIdx.x, nb = gridDim.x;
    int gt = bid*256 + tid;
    int gw = gt >> 5, lane = tid & 31;
    int nwarps = (nb * 256) >> 5;
    const float inv_n = 1.0f / (float)NDOC;

    for (int i = gt; i < NDOC; i += nb*256) g_u1[i] = inv_n;
    gridbar();

    // init: v1 = b1 / (K^T u0 + eps)
    {
        float t = 0.f;
        if (bid < KTOP){
            const float* col = g_KdtT + (size_t)bid * NDOC;
            for (int i = tid; i < NDOC; i += 256) t += col[i] * g_u1[i];
        }
        red[tid] = t; __syncthreads();
        for (int s = 128; s > 0; s >>= 1){ if (tid < s) red[tid] += red[tid+s]; __syncthreads(); }
        if (tid == 0 && bid < KTOP) g_v1[bid] = g_b1[bid] / (red[0] + 1e-16f);
        __syncthreads();
    }
    gridbar();

    float err = 1.0f; int cpt = 0;
    while (err > 0.005f && cpt < 5000){
        // u = a / (K v + eps)   (warp per row)
        for (int i = gw; i < NDOC; i += nwarps){
            const float* row = g_Kdt + (size_t)i * KTOP;
            float t = 0.f;
            for (int j = lane; j < KTOP; j += 32) t += row[j] * g_v1[j];
            t = warp_sum(t);
            if (lane == 0) g_u1[i] = inv_n / (t + 1e-16f);
        }
        gridbar();
        cpt++;
        bool check = (cpt % 50) == 1;
        // s = K^T u ; err uses old v ; v <- b/(s+eps)   (block per column)
        {
            float t = 0.f;
            if (bid < KTOP){
                const float* col = g_KdtT + (size_t)bid * NDOC;
                for (int i = tid; i < NDOC; i += 256) t += col[i] * g_u1[i];
            }
            red[tid] = t; __syncthreads();
            for (int s = 128; s > 0; s >>= 1){ if (tid < s) red[tid] += red[tid+s]; __syncthreads(); }
            if (tid == 0){
                float ep = 0.f;
                if (bid < KTOP){
                    float s = red[0];
                    float vold = g_v1[bid];
                    g_v1fin[bid] = vold;
                    if (check) ep = fabsf(vold * s - g_b1[bid]);
                    g_v1[bid] = g_b1[bid] / (s + 1e-16f);
                }
                if (check) g_errpart[bid] = ep;
            }
            __syncthreads();
        }
        gridbar();
        if (check){
            if (tid == 0){
                float e = 0.f;
                for (int b = 0; b < nb; b++) e += g_errpart[b];
                sh_err = e;
            }
            __syncthreads();
            err = sh_err;
        }
    }
}

// TW: rows KTOP, cols VW. u-phase block-per-row, s/v-phase warp-per-column.
__global__ __launch_bounds__(256) void sink_tw_kernel(){
    __shared__ float red[256];
    __shared__ float sh_err;
    int tid = threadIdx.x, bid = blockIdx.x, nb = gridDim.x;
    int gt = bid*256 + tid;
    int gw = gt >> 5, lane = tid & 31;
    int nwarps = (nb * 256) >> 5;
    const float inv_n = 1.0f / (float)KTOP;

    for (int i = gt; i < KTOP; i += nb*256) g_u2[i] = inv_n;
    gridbar();

    // init v2
    for (int j = gw; j < VW; j += nwarps){
        const float* col = g_KtwT + (size_t)j * KTOP;
        float t = 0.f;
        for (int i = lane; i < KTOP; i += 32) t += col[i] * g_u2[i];
        t = warp_sum(t);
        if (lane == 0) g_v2[j] = g_b2[j] / (t + 1e-16f);
    }
    gridbar();

    float err = 1.0f; int cpt = 0;
    while (err > 0.005f && cpt < 5000){
        // u = a/(K v + eps)  (block per row)
        {
            float t = 0.f;
            if (bid < KTOP){
                const float* row = g_Ktw + (size_t)bid * VW;
                for (int j = tid; j < VW; j += 256) t += row[j] * g_v2[j];
            }
            red[tid] = t; __syncthreads();
            for (int s = 128; s > 0; s >>= 1){ if (tid < s) red[tid] += red[tid+s]; __syncthreads(); }
            if (tid == 0 && bid < KTOP) g_u2[bid] = inv_n / (red[0] + 1e-16f);
            __syncthreads();
        }
        gridbar();
        cpt++;
        bool check = (cpt % 50) == 1;
        // s = K^T u ; err ; v update (warp per column)
        {
            float ep = 0.f;
            for (int j = gw; j < VW; j += nwarps){
                const float* col = g_KtwT + (size_t)j * KTOP;
                float t = 0.f;
                for (int i = lane; i < KTOP; i += 32) t += col[i] * g_u2[i];
                t = warp_sum(t);
                if (lane == 0){
                    float vold = g_v2[j];
                    g_v2fin[j] = vold;
                    if (check) ep += fabsf(vold * t - g_b2[j]);
                    g_v2[j] = g_b2[j] / (t + 1e-16f);
                }
            }
            if (check){
                red[tid] = ep; __syncthreads();
                for (int s = 128; s > 0; s >>= 1){ if (tid < s) red[tid] += red[tid+s]; __syncthreads(); }
                if (tid == 0) g_errpart[bid] = red[0];
                __syncthreads();
            }
        }
        gridbar();
        if (check){
            if (tid == 0){
                float e = 0.f;
                for (int b = 0; b < nb; b++) e += g_errpart[b];
                sh_err = e;
            }
            __syncthreads();
            err = sh_err;
        }
    }
}

// ---------------- transport matrices + transport losses ----------------------
__global__ __launch_bounds__(256) void theta_kernel(){
    __shared__ float red[256];
    int tid = threadIdx.x;
    int g = blockIdx.x*256 + tid, stride = gridDim.x*256;
    float part = 0.f;
    for (int idx = g; idx < NDOC*KTOP; idx += stride){
        int i = idx / KTOP, k = idx - i*KTOP;
        float tr = g_u1[i] * g_Kdt[idx] * g_v1fin[k];
        g_theta[idx] = tr * (float)NDOC;
        part += tr * g_Mdt[idx];
    }
    red[tid] = part; __syncthreads();
    for (int s = 128; s > 0; s >>= 1){ if (tid < s) red[tid] += red[tid+s]; __syncthreads(); }
    if (tid == 0) atomicAdd(&g_acc[0], (double)red[0]);
}

__global__ __launch_bounds__(256) void beta_kernel(){
    __shared__ float red[256];
    int tid = threadIdx.x;
    int g = blockIdx.x*256 + tid, stride = gridDim.x*256;
    float part = 0.f;
    for (int idx = g; idx < KTOP*VW; idx += stride){
        int k = idx / VW, j = idx - k*VW;
        float tr = g_u2[k] * g_Ktw[idx] * g_v2fin[j];
        g_beta[idx] = tr * (float)KTOP;
        part += tr * g_Mtw[idx];
    }
    red[tid] = part; __syncthreads();
    for (int s = 128; s > 0; s >>= 1){ if (tid < s) red[tid] += red[tid+s]; __syncthreads(); }
    if (tid == 0) atomicAdd(&g_acc[1], (double)red[0]);
}

// ---------------- fused recon GEMM + log-loss --------------------------------
// tile: 128 rows x 80 cols, 256 threads (16x16), 8x5 per thread, K-chunks of 25
__global__ __launch_bounds__(256) void recon_kernel(const float* __restrict__ bow){
    __shared__ float As[128*25];
    __shared__ float Bs[25*80];
    __shared__ float red[256];
    int tid = threadIdx.x;
    int tx = tid & 15, ty = tid >> 4;
    int r0 = blockIdx.y * 128;
    int c0 = blockIdx.x * 80;

    float acc[8][5];
#pragma unroll
    for (int i = 0; i < 8; i++)
#pragma unroll
        for (int j = 0; j < 5; j++) acc[i][j] = 0.f;

    for (int kc = 0; kc < 100; kc += 25){
        __syncthreads();
        for (int f = tid; f < 128*25; f += 256){
            int r = f / 25, c = f - r*25;
            As[f] = g_theta[(size_t)(r0 + r)*KTOP + kc + c];
        }
        for (int f = tid; f < 25*80; f += 256){
            int r = f / 80, c = f - r*80;
            Bs[f] = g_beta[(size_t)(kc + r)*VW + c0 + c];
        }
        __syncthreads();
#pragma unroll
        for (int k = 0; k < 25; k++){
            float a[8], b[5];
#pragma unroll
            for (int i = 0; i < 8; i++) a[i] = As[(i*16 + ty)*25 + k];
#pragma unroll
            for (int j = 0; j < 5; j++) b[j] = Bs[k*80 + (j*16 + tx)];
#pragma unroll
            for (int i = 0; i < 8; i++)
#pragma unroll
                for (int j = 0; j < 5; j++) acc[i][j] = fmaf(a[i], b[j], acc[i][j]);
        }
    }

    float part = 0.f;
#pragma unroll
    for (int i = 0; i < 8; i++){
        int r = r0 + i*16 + ty;
        const float* brow = bow + (size_t)r*VW + c0;
#pragma unroll
        for (int j = 0; j < 5; j++){
            part += brow[j*16 + tx] * __logf(acc[i][j] + 1e-12f);
        }
    }
    red[tid] = part; __syncthreads();
    for (int s = 128; s > 0; s >>= 1){ if (tid < s) red[tid] += red[tid+s]; __syncthreads(); }
    if (tid == 0) atomicAdd(&g_acc[2], (double)red[0]);
}

__global__ void final_kernel(float* out){
    out[0] = (float)(g_acc[0] + g_acc[1] - g_acc[2] * (1.0 / (double)NDOC));
}

// ---------------- launch -----------------------------------------------------
extern "C" void kernel_launch(void* const* d_in, const int* in_sizes, int n_in,
                              void* d_out, int out_size)
{
    const float *bow = nullptr, *doc = nullptr, *word = nullptr,
                *topic = nullptr, *ww = nullptr, *tw = nullptr;
    for (int i = 0; i < n_in; i++){
        const float* p = (const float*)d_in[i];
        switch (in_sizes[i]){
            case 40960000: bow = p;   break;   // train_bow [4096,10000]
            case 1572864:  doc = p;   break;   // doc_embeddings [4096,384]
            case 3840000:  word = p;  break;   // word_embeddings [10000,384]
            case 38400:    topic = p; break;   // topic_embeddings [100,384]
            case 10000:    ww = p;    break;   // word_weights
            case 100:      tw = p;    break;   // topic_weights
        }
    }
    float* out = (float*)d_out;

    init_kernel<<<1, 32>>>();

    norms_kernel<<<256, 256>>>(doc,   NDOC, 0);
    norms_kernel<<<16,  256>>>(topic, KTOP, 1);
    norms_kernel<<<256, 256>>>(word,  VW,   2);

    softmax_kernel<<<1, 1024>>>(tw, KTOP, 0);
    softmax_kernel<<<1, 1024>>>(ww, VW,   1);

    // DT distances: doc(4096) x topic(100)
    dist_kernel<<<dim3(2, 64), 256>>>(doc, topic, NDOC, KTOP, 3.0f, 0);
    // TW distances: topic(100) x word(10000)
    dist_kernel<<<dim3(157, 2), 256>>>(topic, word, KTOP, VW, 2.0f, 1);

    sink_dt_kernel<<<148, 256>>>();
    sink_tw_kernel<<<148, 256>>>();

    theta_kernel<<<320, 256>>>();
    beta_kernel<<<512, 256>>>();

    recon_kernel<<<dim3(125, 32), 256>>>(bow);

    final_kernel<<<1, 1>>>(out);
}

// round 10
// speedup vs baseline: 1.8926x; 1.8762x over previous
#include <cuda_runtime.h>
#include <cuda_bf16.h>
#include <math.h>
#include <stdint.h>

#define NDOC 4096
#define VW   10000
#define VWP  10048
#define KTOP 100
#define EDIM 384
#define NC1  48      // DT sinkhorn CTAs
#define NC2  100     // TW sinkhorn CTAs

// ---------------- device state -----------------------------------------------
__device__ float g_Mdt[NDOC*KTOP];
__device__ float g_Kdt[NDOC*KTOP];
__device__ float g_MtwT[VW*KTOP];
__device__ float g_KtwT[VW*KTOP];
__device__ __align__(16) __nv_bfloat16 g_thetaB[NDOC*128];
__device__ __align__(16) __nv_bfloat16 g_betaB[VWP*128];
__device__ float g_u1[NDOC], g_v1fin[KTOP], g_b1[KTOP];
__device__ float g_u2[KTOP], g_v2[VW], g_v2fin[VW], g_b2[VW];
__device__ float g_nd[NDOC], g_nt[KTOP], g_nw[VW];
__device__ float g_part1[2][NC1*128];
__device__ float g_part2[2][NC2*128];
__device__ float g_err2[NC2];
__device__ double g_acc[3];
__device__ unsigned g_bc1, g_bc2;
__device__ volatile unsigned g_bg1, g_bg2;

// ---------------- helpers ----------------------------------------------------
__device__ __forceinline__ float warp_bfly(float v){
    v += __shfl_xor_sync(0xffffffffu, v, 16);
    v += __shfl_xor_sync(0xffffffffu, v, 8);
    v += __shfl_xor_sync(0xffffffffu, v, 4);
    v += __shfl_xor_sync(0xffffffffu, v, 2);
    v += __shfl_xor_sync(0xffffffffu, v, 1);
    return v;
}
__device__ __forceinline__ float warp_sum(float v){
    v += __shfl_down_sync(0xffffffffu, v, 16);
    v += __shfl_down_sync(0xffffffffu, v, 8);
    v += __shfl_down_sync(0xffffffffu, v, 4);
    v += __shfl_down_sync(0xffffffffu, v, 2);
    v += __shfl_down_sync(0xffffffffu, v, 1);
    return v;
}
__device__ __forceinline__ void gbar(unsigned* cnt, volatile unsigned* gen, unsigned nb){
    __syncthreads();
    if (threadIdx.x == 0){
        __threadfence();
        unsigned g = *gen;
        if (atomicAdd(cnt, 1u) == nb - 1u){
            *cnt = 0u; __threadfence(); *gen = g + 1u;
        } else {
            while (*gen == g) { __nanosleep(32); }
            __threadfence();
        }
    }
    __syncthreads();
}

// ---------------- setup ------------------------------------------------------
__global__ void init_kernel(){
    if (threadIdx.x == 0){
        g_bc1 = 0u; g_bc2 = 0u; g_bg1 = 0u; g_bg2 = 0u;
        g_acc[0] = 0.0; g_acc[1] = 0.0; g_acc[2] = 0.0;
    }
}

__global__ void norms_kernel(const float* __restrict__ x, int n, int sel){
    float* out = (sel == 0) ? g_nd : ((sel == 1) ? g_nt : g_nw);
    int gt = blockIdx.x * blockDim.x + threadIdx.x;
    int gw = gt >> 5, lane = threadIdx.x & 31;
    int nw = (gridDim.x * blockDim.x) >> 5;
    for (int i = gw; i < n; i += nw){
        const float* row = x + (size_t)i * EDIM;
        float s = 0.f;
        for (int e = lane; e < EDIM; e += 32){ float t = row[e]; s += t * t; }
        s = warp_sum(s);
        if (lane == 0) out[i] = s;
    }
}

__global__ void softmax_kernel(const float* __restrict__ x, int n, int sel){
    float* out = (sel == 0) ? g_b1 : g_b2;
    __shared__ float red[1024];
    int tid = threadIdx.x, nt = blockDim.x;
    float m = -3.4e38f;
    for (int i = tid; i < n; i += nt) m = fmaxf(m, x[i]);
    red[tid] = m; __syncthreads();
    for (int s = nt >> 1; s > 0; s >>= 1){ if (tid < s) red[tid] = fmaxf(red[tid], red[tid+s]); __syncthreads(); }
    m = red[0]; __syncthreads();
    float sum = 0.f;
    for (int i = tid; i < n; i += nt) sum += expf(x[i] - m);
    red[tid] = sum; __syncthreads();
    for (int s = nt >> 1; s > 0; s >>= 1){ if (tid < s) red[tid] += red[tid+s]; __syncthreads(); }
    sum = red[0]; __syncthreads();
    float inv = 1.0f / sum;
    for (int i = tid; i < n; i += nt) out[i] = expf(x[i] - m) * inv;
}

// which: 0 = DT -> row-major Mdt/Kdt ; 1 = TW -> transposed MtwT/KtwT
__global__ __launch_bounds__(256) void dist_kernel(
    const float* __restrict__ A, const float* __restrict__ B,
    int nA, int nB, float alpha, int which)
{
    const float* nAarr = which ? g_nt : g_nd;
    const float* nBarr = which ? g_nw : g_nt;
    __shared__ float As[64*33];
    __shared__ float Bs[64*33];
    int tid = threadIdx.x;
    int tx = tid & 15, ty = tid >> 4;
    int r0 = blockIdx.y * 64, c0 = blockIdx.x * 64;

    float acc[4][4];
#pragma unroll
    for (int i = 0; i < 4; i++)
#pragma unroll
        for (int j = 0; j < 4; j++) acc[i][j] = 0.f;

    for (int ec = 0; ec < EDIM; ec += 32){
        __syncthreads();
        for (int f = tid; f < 64*32; f += 256){
            int r = f >> 5, c = f & 31;
            As[r*33 + c] = (r0 + r < nA) ? A[(size_t)(r0 + r)*EDIM + ec + c] : 0.f;
            Bs[r*33 + c] = (c0 + r < nB) ? B[(size_t)(c0 + r)*EDIM + ec + c] : 0.f;
        }
        __syncthreads();
#pragma unroll
        for (int e = 0; e < 32; e++){
            float a[4], b[4];
#pragma unroll
            for (int i = 0; i < 4; i++) a[i] = As[(i*16 + ty)*33 + e];
#pragma unroll
            for (int j = 0; j < 4; j++) b[j] = Bs[(j*16 + tx)*33 + e];
#pragma unroll
            for (int i = 0; i < 4; i++)
#pragma unroll
                for (int j = 0; j < 4; j++) acc[i][j] = fmaf(a[i], b[j], acc[i][j]);
        }
    }
#pragma unroll
    for (int i = 0; i < 4; i++){
        int r = r0 + i*16 + ty;
        if (r >= nA) continue;
#pragma unroll
        for (int j = 0; j < 4; j++){
            int c = c0 + j*16 + tx;
            if (c >= nB) continue;
            float M = nAarr[r] + nBarr[c] - 2.0f * acc[i][j];
            float kv = expf(-alpha * M);
            if (which == 0){
                g_Mdt[(size_t)r*KTOP + c] = M;
                g_Kdt[(size_t)r*KTOP + c] = kv;
            } else {
                g_MtwT[(size_t)c*KTOP + r] = M;
                g_KtwT[(size_t)c*KTOP + r] = kv;
            }
        }
    }
}

// ---------------- fused persistent Sinkhorn ----------------------------------
__device__ void sink_dt(int cta){
    __shared__ float v_sm[128], vf_sm[128], b_sm[128], spw[8][128], red[256];
    int tid = threadIdx.x, w = tid >> 5, lane = tid & 31;
    int gwid = cta*8 + w;
    const int NWRP = NC1*8;
    const float invN = 1.0f / (float)NDOC;

    if (tid < 128) b_sm[tid] = (tid < 100) ? g_b1[tid] : 0.f;
    // prologue partials: s0 = K^T u0, u0 = 1/N
    {
        float p0=0.f,p1=0.f,p2=0.f,p3=0.f;
        for (int i = gwid; i < NDOC; i += NWRP){
            const float* row = g_Kdt + (size_t)i*KTOP;
            p0 += row[lane]; p1 += row[lane+32]; p2 += row[lane+64];
            if (lane < 4) p3 += row[lane+96];
        }
        spw[w][lane] = p0*invN; spw[w][lane+32] = p1*invN; spw[w][lane+64] = p2*invN;
        spw[w][lane+96] = (lane < 4) ? p3*invN : 0.f;
    }
    __syncthreads();
    if (tid < 100){
        float s = 0.f;
#pragma unroll
        for (int x = 0; x < 8; x++) s += spw[x][tid];
        g_part1[0][cta*128 + tid] = s;
    }
    gbar(&g_bc1, &g_bg1, NC1);
    if (tid < 128){
        float s = 0.f;
        if (tid < 100){
#pragma unroll 8
            for (int cc = 0; cc < NC1; cc++) s += g_part1[0][cc*128 + tid];
            v_sm[tid] = b_sm[tid] / (s + 1e-16f);
        } else v_sm[tid] = 0.f;
    }
    __syncthreads();

    float err = 1.0f; int cpt = 0, buf = 1;
    while (err > 0.005f && cpt < 5000){
        float v0 = v_sm[lane], v1 = v_sm[lane+32], v2 = v_sm[lane+64], v3 = v_sm[lane+96];
        float p0=0.f,p1=0.f,p2=0.f,p3=0.f;
        for (int i = gwid; i < NDOC; i += NWRP){
            const float* row = g_Kdt + (size_t)i*KTOP;
            float k0 = row[lane], k1 = row[lane+32], k2 = row[lane+64];
            float k3 = (lane < 4) ? row[lane+96] : 0.f;
            float t = warp_bfly(k0*v0 + k1*v1 + k2*v2 + k3*v3);
            float u = invN / (t + 1e-16f);
            if (lane == 0) g_u1[i] = u;
            p0 += k0*u; p1 += k1*u; p2 += k2*u; p3 += k3*u;
        }
        spw[w][lane] = p0; spw[w][lane+32] = p1; spw[w][lane+64] = p2;
        spw[w][lane+96] = (lane < 4) ? p3 : 0.f;
        __syncthreads();
        if (tid < 100){
            float s = 0.f;
#pragma unroll
            for (int x = 0; x < 8; x++) s += spw[x][tid];
            g_part1[buf][cta*128 + tid] = s;
        }
        cpt++;
        bool check = (cpt % 50) == 1;
        gbar(&g_bc1, &g_bg1, NC1);
        float ev = 0.f;
        if (tid < 128){
            float s = 0.f;
            if (tid < 100){
#pragma unroll 8
                for (int cc = 0; cc < NC1; cc++) s += g_part1[buf][cc*128 + tid];
            }
            float vo = v_sm[tid];
            vf_sm[tid] = vo;
            if (check && tid < 100) ev = fabsf(vo*s - b_sm[tid]);
            v_sm[tid] = (tid < 100) ? (b_sm[tid] / (s + 1e-16f)) : 0.f;
        }
        if (check){
            red[tid] = ev; __syncthreads();
            for (int s2 = 128; s2 > 0; s2 >>= 1){ if (tid < s2) red[tid] += red[tid+s2]; __syncthreads(); }
            err = red[0];
        }
        __syncthreads();
        buf ^= 1;
    }
    if (cta == 0 && tid < 100) g_v1fin[tid] = vf_sm[tid];
}

__device__ void sink_tw(int cta){
    __shared__ float u_sm[128], spw[8][128], red[256];
    __shared__ float errsh;
    int tid = threadIdx.x, w = tid >> 5, lane = tid & 31;
    int gwid = cta*8 + w;
    const int NWRP = NC2*8;
    const float invK = 1.0f / (float)KTOP;

    // prologue: v1 = b/(K^T u0), partials r1 = K v1
    {
        float p0=0.f,p1=0.f,p2=0.f,p3=0.f;
        for (int j = gwid; j < VW; j += NWRP){
            const float* rowt = g_KtwT + (size_t)j*KTOP;
            float k0 = rowt[lane], k1 = rowt[lane+32], k2 = rowt[lane+64];
            float k3 = (lane < 4) ? rowt[lane+96] : 0.f;
            float t = warp_bfly(k0 + k1 + k2 + k3) * invK;
            float v = g_b2[j] / (t + 1e-16f);
            if (lane == 0) g_v2[j] = v;
            p0 += k0*v; p1 += k1*v; p2 += k2*v; p3 += k3*v;
        }
        spw[w][lane] = p0; spw[w][lane+32] = p1; spw[w][lane+64] = p2;
        spw[w][lane+96] = (lane < 4) ? p3 : 0.f;
    }
    __syncthreads();
    if (tid < 100){
        float s = 0.f;
#pragma unroll
        for (int x = 0; x < 8; x++) s += spw[x][tid];
        g_part2[0][cta*128 + tid] = s;
    }
    gbar(&g_bc2, &g_bg2, NC2);

    float err = 1.0f; int cpt = 0, buf = 1;
    while (err > 0.005f && cpt < 5000){
        if (tid < 128){
            float r = 0.f;
            if (tid < 100){
#pragma unroll 10
                for (int cc = 0; cc < NC2; cc++) r += g_part2[buf^1][cc*128 + tid];
                u_sm[tid] = invK / (r + 1e-16f);
            } else u_sm[tid] = 0.f;
        }
        __syncthreads();
        cpt++;
        bool check = (cpt % 50) == 1;
        float u0 = u_sm[lane], u1 = u_sm[lane+32], u2 = u_sm[lane+64], u3 = u_sm[lane+96];
        float p0=0.f,p1=0.f,p2=0.f,p3=0.f, ep = 0.f;
        for (int j = gwid; j < VW; j += NWRP){
            const float* rowt = g_KtwT + (size_t)j*KTOP;
            float k0 = rowt[lane], k1 = rowt[lane+32], k2 = rowt[lane+64];
            float k3 = (lane < 4) ? rowt[lane+96] : 0.f;
            float t = warp_bfly(k0*u0 + k1*u1 + k2*u2 + k3*u3);
            float bj = g_b2[j];
            float vn = bj / (t + 1e-16f);
            if (lane == 0){
                float vo = g_v2[j];
                if (check) ep += fabsf(vo*t - bj);
                g_v2fin[j] = vo;
                g_v2[j] = vn;
            }
            p0 += k0*vn; p1 += k1*vn; p2 += k2*vn; p3 += k3*vn;
        }
        spw[w][lane] = p0; spw[w][lane+32] = p1; spw[w][lane+64] = p2;
        spw[w][lane+96] = (lane < 4) ? p3 : 0.f;
        if (check){
            red[tid] = ep; __syncthreads();
            for (int s2 = 128; s2 > 0; s2 >>= 1){ if (tid < s2) red[tid] += red[tid+s2]; __syncthreads(); }
            if (tid == 0) g_err2[cta] = red[0];
        }
        __syncthreads();
        if (tid < 100){
            float s = 0.f;
#pragma unroll
            for (int x = 0; x < 8; x++) s += spw[x][tid];
            g_part2[buf][cta*128 + tid] = s;
        }
        gbar(&g_bc2, &g_bg2, NC2);
        if (check){
            if (tid == 0){
                float e = 0.f;
                for (int cc = 0; cc < NC2; cc++) e += g_err2[cc];
                errsh = e;
            }
            __syncthreads();
            err = errsh;
        }
        buf ^= 1;
    }
    if (cta == 0 && tid < 100) g_u2[tid] = u_sm[tid];
}

__global__ __launch_bounds__(256) void sink_fused(){
    if (blockIdx.x < NC1) sink_dt(blockIdx.x);
    else                  sink_tw(blockIdx.x - NC1);
}

// ---------------- theta/beta (bf16 padded) + transport losses ----------------
__global__ __launch_bounds__(256) void theta_kernel(){
    __shared__ float red[256];
    int tid = threadIdx.x;
    int g = blockIdx.x*256 + tid, stride = gridDim.x*256;
    float part = 0.f;
    for (int idx = g; idx < NDOC*128; idx += stride){
        int i = idx >> 7, k = idx & 127;
        float o = 0.f;
        if (k < KTOP){
            float tr = g_u1[i] * g_Kdt[(size_t)i*KTOP + k] * g_v1fin[k];
            o = tr * (float)NDOC;
            part += tr * g_Mdt[(size_t)i*KTOP + k];
        }
        g_thetaB[idx] = __float2bfloat16(o);
    }
    red[tid] = part; __syncthreads();
    for (int s = 128; s > 0; s >>= 1){ if (tid < s) red[tid] += red[tid+s]; __syncthreads(); }
    if (tid == 0) atomicAdd(&g_acc[0], (double)red[0]);
}

__global__ __launch_bounds__(256) void beta_kernel(){
    __shared__ float red[256];
    int tid = threadIdx.x;
    int g = blockIdx.x*256 + tid, stride = gridDim.x*256;
    float part = 0.f;
    for (int idx = g; idx < VWP*128; idx += stride){
        int j = idx >> 7, k = idx & 127;
        float o = 0.f;
        if (j < VW && k < KTOP){
            float tr = g_u2[k] * g_KtwT[(size_t)j*KTOP + k] * g_v2fin[j];
            o = tr * (float)KTOP;
            part += tr * g_MtwT[(size_t)j*KTOP + k];
        }
        g_betaB[idx] = __float2bfloat16(o);
    }
    red[tid] = part; __syncthreads();
    for (int s = 128; s > 0; s >>= 1){ if (tid < s) red[tid] += red[tid+s]; __syncthreads(); }
    if (tid == 0) atomicAdd(&g_acc[1], (double)red[0]);
}

// ---------------- tensor-core recon GEMM + log-loss --------------------------
// CTA 128x64, 8 warps (4x2) of 32x32, mma.sync m16n8k16 bf16, K=128 in 2 chunks
__global__ __launch_bounds__(256) void recon_kernel(const float* __restrict__ bow){
    __shared__ __nv_bfloat16 As[128*72];
    __shared__ __nv_bfloat16 Bs[64*72];
    __shared__ float red[256];
    int tid = threadIdx.x, lane = tid & 31, w = tid >> 5;
    int wr = w >> 1, wc = w & 1;
    int g = lane >> 2, c = lane & 3;
    int r0 = blockIdx.y * 128, c0 = blockIdx.x * 64;

    float acc[2][4][4];
#pragma unroll
    for (int mi = 0; mi < 2; mi++)
#pragma unroll
        for (int ni = 0; ni < 4; ni++)
#pragma unroll
            for (int q = 0; q < 4; q++) acc[mi][ni][q] = 0.f;

    const uint32_t* Aw = (const uint32_t*)As;
    const uint32_t* Bw = (const uint32_t*)Bs;
    int rabase = (wr*32 + g)*36;
    int rbbase = (wc*32 + g)*36;

    for (int chunk = 0; chunk < 2; chunk++){
        __syncthreads();
        for (int f = tid; f < 1024; f += 256){
            int r = f >> 3, q = f & 7;
            uint4 val = *(const uint4*)&g_thetaB[(size_t)(r0 + r)*128 + chunk*64 + q*8];
            *(uint4*)&As[r*72 + q*8] = val;
        }
        for (int f = tid; f < 512; f += 256){
            int r = f >> 3, q = f & 7;
            uint4 val = *(const uint4*)&g_betaB[(size_t)(c0 + r)*128 + chunk*64 + q*8];
            *(uint4*)&Bs[r*72 + q*8] = val;
        }
        __syncthreads();
#pragma unroll
        for (int ks = 0; ks < 4; ks++){
            int ka = ks*8 + c;
            uint32_t a0[2], a1[2], a2[2], a3[2], b0[4], b1[4];
#pragma unroll
            for (int mi = 0; mi < 2; mi++){
                int base = rabase + mi*16*36 + ka;
                a0[mi] = Aw[base]; a1[mi] = Aw[base + 8*36];
                a2[mi] = Aw[base + 4]; a3[mi] = Aw[base + 8*36 + 4];
            }
#pragma unroll
            for (int ni = 0; ni < 4; ni++){
                int base = rbbase + ni*8*36 + ka;
                b0[ni] = Bw[base]; b1[ni] = Bw[base + 4];
            }
#pragma unroll
            for (int mi = 0; mi < 2; mi++)
#pragma unroll
                for (int ni = 0; ni < 4; ni++){
                    asm volatile(
                        "mma.sync.aligned.m16n8k16.row.col.f32.bf16.bf16.f32 "
                        "{%0,%1,%2,%3}, {%4,%5,%6,%7}, {%8,%9}, {%0,%1,%2,%3};"
                        : "+f"(acc[mi][ni][0]), "+f"(acc[mi][ni][1]),
                          "+f"(acc[mi][ni][2]), "+f"(acc[mi][ni][3])
                        : "r"(a0[mi]), "r"(a1[mi]), "r"(a2[mi]), "r"(a3[mi]),
                          "r"(b0[ni]), "r"(b1[ni]));
                }
        }
    }

    float part = 0.f;
#pragma unroll
    for (int mi = 0; mi < 2; mi++){
        int R = r0 + wr*32 + mi*16 + g;
#pragma unroll
        for (int ni = 0; ni < 4; ni++){
            int C = c0 + wc*32 + ni*8 + c*2;
            if (C < VW){
                float2 bw = *(const float2*)&bow[(size_t)R*VW + C];
                part += bw.x * __logf(acc[mi][ni][0] + 1e-12f)
                      + bw.y * __logf(acc[mi][ni][1] + 1e-12f);
                float2 bw2 = *(const float2*)&bow[(size_t)(R + 8)*VW + C];
                part += bw2.x * __logf(acc[mi][ni][2] + 1e-12f)
                      + bw2.y * __logf(acc[mi][ni][3] + 1e-12f);
            }
        }
    }
    red[tid] = part; __syncthreads();
    for (int s = 128; s > 0; s >>= 1){ if (tid < s) red[tid] += red[tid+s]; __syncthreads(); }
    if (tid == 0) atomicAdd(&g_acc[2], (double)red[0]);
}

__global__ void final_kernel(float* out){
    out[0] = (float)(g_acc[0] + g_acc[1] - g_acc[2] * (1.0 / (double)NDOC));
}

// ---------------- launch -----------------------------------------------------
extern "C" void kernel_launch(void* const* d_in, const int* in_sizes, int n_in,
                              void* d_out, int out_size)
{
    const float *bow = nullptr, *doc = nullptr, *word = nullptr,
                *topic = nullptr, *ww = nullptr, *tw = nullptr;
    for (int i = 0; i < n_in; i++){
        const float* p = (const float*)d_in[i];
        switch (in_sizes[i]){
            case 40960000: bow = p;   break;
            case 1572864:  doc = p;   break;
            case 3840000:  word = p;  break;
            case 38400:    topic = p; break;
            case 10000:    ww = p;    break;
            case 100:      tw = p;    break;
        }
    }
    float* out = (float*)d_out;

    init_kernel<<<1, 32>>>();

    norms_kernel<<<256, 256>>>(doc,   NDOC, 0);
    norms_kernel<<<16,  256>>>(topic, KTOP, 1);
    norms_kernel<<<256, 256>>>(word,  VW,   2);

    softmax_kernel<<<1, 1024>>>(tw, KTOP, 0);
    softmax_kernel<<<1, 1024>>>(ww, VW,   1);

    dist_kernel<<<dim3(2, 64), 256>>>(doc, topic, NDOC, KTOP, 3.0f, 0);
    dist_kernel<<<dim3(157, 2), 256>>>(topic, word, KTOP, VW, 2.0f, 1);

    sink_fused<<<NC1 + NC2, 256>>>();

    theta_kernel<<<320, 256>>>();
    beta_kernel<<<512, 256>>>();

    recon_kernel<<<dim3(157, 32), 256>>>(bow);

    final_kernel<<<1, 1>>>(out);
}

// round 11
// speedup vs baseline: 2.2896x; 1.2098x over previous
#include <cuda_runtime.h>
#include <cuda_bf16.h>
#include <math.h>
#include <stdint.h>

#define NDOC 4096
#define VW   10000
#define VWP  10048
#define KTOP 100
#define EDIM 384
#define NC1  44      // DT sinkhorn CTAs
#define NC2  104     // TW sinkhorn CTAs

// ---------------- device state -----------------------------------------------
__device__ __align__(16) float g_Mdt[NDOC*KTOP];
__device__ __align__(16) float g_Kdt[NDOC*KTOP];
__device__ __align__(16) float g_MtwT[VW*KTOP];
__device__ __align__(16) float g_KtwT[VW*KTOP];
__device__ __align__(16) __nv_bfloat16 g_thetaB[NDOC*128];
__device__ __align__(16) __nv_bfloat16 g_betaB[VWP*128];
__device__ float g_u1[NDOC], g_v1fin[KTOP], g_b1[KTOP];
__device__ float g_u2[KTOP], g_v2[VW], g_v2fin[VW], g_b2[VW];
__device__ float g_nd[NDOC], g_nt[KTOP], g_nw[VW];
__device__ float g_part1[2][NC1*128];
__device__ float g_part2[2][NC2*128];
__device__ float g_err2[NC2];
__device__ double g_acc[3];
__device__ unsigned g_bc1, g_bc2;
__device__ volatile unsigned g_bg1, g_bg2;

// ---------------- helpers ----------------------------------------------------
__device__ __forceinline__ float warp_bfly(float v){
    v += __shfl_xor_sync(0xffffffffu, v, 16);
    v += __shfl_xor_sync(0xffffffffu, v, 8);
    v += __shfl_xor_sync(0xffffffffu, v, 4);
    v += __shfl_xor_sync(0xffffffffu, v, 2);
    v += __shfl_xor_sync(0xffffffffu, v, 1);
    return v;
}
__device__ __forceinline__ float warp_sum(float v){
    v += __shfl_down_sync(0xffffffffu, v, 16);
    v += __shfl_down_sync(0xffffffffu, v, 8);
    v += __shfl_down_sync(0xffffffffu, v, 4);
    v += __shfl_down_sync(0xffffffffu, v, 2);
    v += __shfl_down_sync(0xffffffffu, v, 1);
    return v;
}
__device__ __forceinline__ void gbar(unsigned* cnt, volatile unsigned* gen, unsigned nb){
    __syncthreads();
    if (threadIdx.x == 0){
        __threadfence();
        unsigned g = *gen;
        if (atomicAdd(cnt, 1u) == nb - 1u){
            *cnt = 0u; __threadfence(); *gen = g + 1u;
        } else {
            while (*gen == g) { __nanosleep(32); }
            __threadfence();
        }
    }
    __syncthreads();
}

// ---------------- fused prologue: init + norms + softmax ----------------------
__global__ __launch_bounds__(256) void prologue_kernel(
    const float* __restrict__ doc, const float* __restrict__ topic,
    const float* __restrict__ word, const float* __restrict__ tw,
    const float* __restrict__ ww)
{
    __shared__ float red[256];
    int b = blockIdx.x, tid = threadIdx.x;
    if (b < 148){
        int lane = tid & 31, w = tid >> 5;
        int gw = b*8 + w;
        const int TOT = NDOC + KTOP + VW;
        for (int row = gw; row < TOT; row += 148*8){
            const float4* src; float* dst;
            if (row < NDOC){ src = (const float4*)(doc + (size_t)row*EDIM); dst = &g_nd[row]; }
            else if (row < NDOC + KTOP){ src = (const float4*)(topic + (size_t)(row-NDOC)*EDIM); dst = &g_nt[row-NDOC]; }
            else { src = (const float4*)(word + (size_t)(row-NDOC-KTOP)*EDIM); dst = &g_nw[row-NDOC-KTOP]; }
            float4 a = src[lane], c = src[lane+32], d = src[lane+64];
            float s = a.x*a.x + a.y*a.y + a.z*a.z + a.w*a.w
                    + c.x*c.x + c.y*c.y + c.z*c.z + c.w*c.w
                    + d.x*d.x + d.y*d.y + d.z*d.z + d.w*d.w;
            s = warp_sum(s);
            if (lane == 0) *dst = s;
        }
    } else if (b == 148 || b == 149){
        const float* x = (b == 148) ? tw : ww;
        float* out = (b == 148) ? g_b1 : g_b2;
        int n = (b == 148) ? KTOP : VW;
        float m = -3.4e38f;
        for (int i = tid; i < n; i += 256) m = fmaxf(m, x[i]);
        red[tid] = m; __syncthreads();
        for (int s = 128; s > 0; s >>= 1){ if (tid < s) red[tid] = fmaxf(red[tid], red[tid+s]); __syncthreads(); }
        m = red[0]; __syncthreads();
        float sum = 0.f;
        for (int i = tid; i < n; i += 256) sum += expf(x[i] - m);
        red[tid] = sum; __syncthreads();
        for (int s = 128; s > 0; s >>= 1){ if (tid < s) red[tid] += red[tid+s]; __syncthreads(); }
        sum = red[0]; __syncthreads();
        float inv = 1.0f / sum;
        for (int i = tid; i < n; i += 256) out[i] = expf(x[i] - m) * inv;
    } else {
        if (tid == 0){
            g_bc1 = 0u; g_bc2 = 0u; g_bg1 = 0u; g_bg2 = 0u;
            g_acc[0] = 0.0; g_acc[1] = 0.0; g_acc[2] = 0.0;
        }
    }
}

// ---------------- tf32 tensor-core distance kernel ----------------------------
// one CTA: 128 rows (doc or word) x 128 cols (topics, 100 valid), K=384 in 12x32
// blockIdx < 32 -> DT (doc rows, alpha=3, out row-major), else TW (word rows,
// alpha=2, out transposed word-major). Both outputs are [R*100 + C].
__global__ __launch_bounds__(256) void dist_mma(
    const float* __restrict__ doc, const float* __restrict__ word,
    const float* __restrict__ topic)
{
    __shared__ float As[128*36];
    __shared__ float Bs[128*36];
    int tid = threadIdx.x, lane = tid & 31, w = tid >> 5;
    int wr = w >> 1, wc = w & 1;
    int g = lane >> 2, c = lane & 3;
    int by = blockIdx.x;
    bool dt = (by < 32);
    const float* A = dt ? doc : word;
    int nA = dt ? NDOC : VW;
    int r0 = (dt ? by : (by - 32)) * 128;
    float alpha = dt ? 3.0f : 2.0f;
    const float* nAarr = dt ? g_nd : g_nw;
    float* Mo = dt ? g_Mdt : g_MtwT;
    float* Ko = dt ? g_Kdt : g_KtwT;

    float acc[2][8][4];
#pragma unroll
    for (int mi = 0; mi < 2; mi++)
#pragma unroll
        for (int ni = 0; ni < 8; ni++)
#pragma unroll
            for (int q = 0; q < 4; q++) acc[mi][ni][q] = 0.f;

    for (int chunk = 0; chunk < 12; chunk++){
        int kc = chunk * 32;
        __syncthreads();
        for (int f = tid; f < 1024; f += 256){
            int r = f >> 3, q = f & 7;
            float4 v = make_float4(0,0,0,0);
            if (r0 + r < nA) v = *(const float4*)&A[(size_t)(r0 + r)*EDIM + kc + q*4];
            *(float4*)&As[r*36 + q*4] = v;
        }
        for (int f = tid; f < 1024; f += 256){
            int r = f >> 3, q = f & 7;
            float4 v = make_float4(0,0,0,0);
            if (r < KTOP) v = *(const float4*)&topic[(size_t)r*EDIM + kc + q*4];
            *(float4*)&Bs[r*36 + q*4] = v;
        }
        __syncthreads();
#pragma unroll
        for (int ks = 0; ks < 4; ks++){
            int ka = ks*8 + c;
            uint32_t a0[2], a1[2], a2[2], a3[2], b0[8], b1[8];
#pragma unroll
            for (int mi = 0; mi < 2; mi++){
                int base = (wr*32 + mi*16 + g)*36 + ka;
                a0[mi] = __float_as_uint(As[base]);
                a1[mi] = __float_as_uint(As[base + 8*36]);
                a2[mi] = __float_as_uint(As[base + 4]);
                a3[mi] = __float_as_uint(As[base + 8*36 + 4]);
            }
#pragma unroll
            for (int ni = 0; ni < 8; ni++){
                int nb = (wc*64 + ni*8 + g)*36 + ka;
                b0[ni] = __float_as_uint(Bs[nb]);
                b1[ni] = __float_as_uint(Bs[nb + 4]);
            }
#pragma unroll
            for (int mi = 0; mi < 2; mi++)
#pragma unroll
                for (int ni = 0; ni < 8; ni++){
                    asm volatile(
                        "mma.sync.aligned.m16n8k8.row.col.f32.tf32.tf32.f32 "
                        "{%0,%1,%2,%3}, {%4,%5,%6,%7}, {%8,%9}, {%0,%1,%2,%3};"
                        : "+f"(acc[mi][ni][0]), "+f"(acc[mi][ni][1]),
                          "+f"(acc[mi][ni][2]), "+f"(acc[mi][ni][3])
                        : "r"(a0[mi]), "r"(a1[mi]), "r"(a2[mi]), "r"(a3[mi]),
                          "r"(b0[ni]), "r"(b1[ni]));
                }
        }
    }

#pragma unroll
    for (int mi = 0; mi < 2; mi++){
        int Rb = r0 + wr*32 + mi*16 + g;
#pragma unroll
        for (int ni = 0; ni < 8; ni++){
            int Cb = wc*64 + ni*8 + c*2;
#pragma unroll
            for (int q = 0; q < 4; q++){
                int R = Rb + ((q >= 2) ? 8 : 0);
                int C = Cb + (q & 1);
                if (R < nA && C < KTOP){
                    float M = nAarr[R] + g_nt[C] - 2.0f * acc[mi][ni][q];
                    float kv = expf(-alpha * M);
                    Mo[(size_t)R*KTOP + C] = M;
                    Ko[(size_t)R*KTOP + C] = kv;
                }
            }
        }
    }
}

// ---------------- fused persistent Sinkhorn ----------------------------------
__device__ void sink_dt(int cta){
    __shared__ float v_sm[128], vf_sm[128], b_sm[128], spw[8][128], red[256], r2[256];
    int tid = threadIdx.x, w = tid >> 5, lane = tid & 31;
    int gwid = cta*8 + w;
    const int NWRP = NC1*8;
    const float invN = 1.0f / (float)NDOC;

    if (tid < 128) b_sm[tid] = (tid < 100) ? g_b1[tid] : 0.f;
    // prologue: s0 = K^T u0 with u0 = 1/N
    {
        float4 p = make_float4(0,0,0,0);
        for (int i = gwid; i < NDOC; i += NWRP){
            if (lane < 25){
                float4 k = ((const float4*)(g_Kdt + (size_t)i*KTOP))[lane];
                p.x += k.x; p.y += k.y; p.z += k.z; p.w += k.w;
            }
        }
        if (lane < 25){
            spw[w][4*lane]   = p.x*invN; spw[w][4*lane+1] = p.y*invN;
            spw[w][4*lane+2] = p.z*invN; spw[w][4*lane+3] = p.w*invN;
        }
    }
    __syncthreads();
    if (tid < 100){
        float s = 0.f;
#pragma unroll
        for (int x = 0; x < 8; x++) s += spw[x][tid];
        g_part1[0][cta*128 + tid] = s;
    }
    gbar(&g_bc1, &g_bg1, NC1);
    if (tid < 200){
        int col = (tid < 100) ? tid : (tid - 100);
        int lo = (tid < 100) ? 0 : (NC1/2), hi = (tid < 100) ? (NC1/2) : NC1;
        float s = 0.f;
        for (int cc = lo; cc < hi; cc++) s += g_part1[0][cc*128 + col];
        r2[tid] = s;
    }
    __syncthreads();
    if (tid < 128) v_sm[tid] = (tid < 100) ? (b_sm[tid] / (r2[tid] + r2[tid+100] + 1e-16f)) : 0.f;
    __syncthreads();

    float err = 1.0f; int cpt = 0, buf = 1;
    while (err > 0.005f && cpt < 5000){
        float4 vv = (lane < 25) ? ((const float4*)v_sm)[lane] : make_float4(0,0,0,0);
        float4 p = make_float4(0,0,0,0);
        for (int i = gwid; i < NDOC; i += 2*NWRP){
            int i2 = i + NWRP;
            float4 ka = make_float4(0,0,0,0), kb = make_float4(0,0,0,0);
            if (lane < 25){
                ka = ((const float4*)(g_Kdt + (size_t)i*KTOP))[lane];
                if (i2 < NDOC) kb = ((const float4*)(g_Kdt + (size_t)i2*KTOP))[lane];
            }
            float ta = ka.x*vv.x + ka.y*vv.y + ka.z*vv.z + ka.w*vv.w;
            float tb = kb.x*vv.x + kb.y*vv.y + kb.z*vv.z + kb.w*vv.w;
            ta = warp_bfly(ta); tb = warp_bfly(tb);
            float ua = invN / (ta + 1e-16f);
            if (lane == 0) g_u1[i] = ua;
            p.x += ka.x*ua; p.y += ka.y*ua; p.z += ka.z*ua; p.w += ka.w*ua;
            if (i2 < NDOC){
                float ub = invN / (tb + 1e-16f);
                if (lane == 0) g_u1[i2] = ub;
                p.x += kb.x*ub; p.y += kb.y*ub; p.z += kb.z*ub; p.w += kb.w*ub;
            }
        }
        if (lane < 25){
            spw[w][4*lane] = p.x; spw[w][4*lane+1] = p.y;
            spw[w][4*lane+2] = p.z; spw[w][4*lane+3] = p.w;
        }
        __syncthreads();
        if (tid < 100){
            float s = 0.f;
#pragma unroll
            for (int x = 0; x < 8; x++) s += spw[x][tid];
            g_part1[buf][cta*128 + tid] = s;
        }
        cpt++;
        bool check = (cpt % 50) == 1;
        gbar(&g_bc1, &g_bg1, NC1);
        if (tid < 200){
            int col = (tid < 100) ? tid : (tid - 100);
            int lo = (tid < 100) ? 0 : (NC1/2), hi = (tid < 100) ? (NC1/2) : NC1;
            float s = 0.f;
            for (int cc = lo; cc < hi; cc++) s += g_part1[buf][cc*128 + col];
            r2[tid] = s;
        }
        __syncthreads();
        float ev = 0.f;
        if (tid < 128){
            float s = (tid < 100) ? (r2[tid] + r2[tid+100]) : 0.f;
            float vo = v_sm[tid];
            vf_sm[tid] = vo;
            if (check && tid < 100) ev = fabsf(vo*s - b_sm[tid]);
            v_sm[tid] = (tid < 100) ? (b_sm[tid] / (s + 1e-16f)) : 0.f;
        }
        if (check){
            red[tid] = ev; __syncthreads();
            for (int s2 = 128; s2 > 0; s2 >>= 1){ if (tid < s2) red[tid] += red[tid+s2]; __syncthreads(); }
            err = red[0];
        }
        __syncthreads();
        buf ^= 1;
    }
    if (cta == 0 && tid < 100) g_v1fin[tid] = vf_sm[tid];
}

__device__ void sink_tw(int cta){
    __shared__ float u_sm[128], spw[8][128], red[256], r2[256];
    int tid = threadIdx.x, w = tid >> 5, lane = tid & 31;
    int gwid = cta*8 + w;
    const int NWRP = NC2*8;
    const float invK = 1.0f / (float)KTOP;

    // prologue: v1 = b/(K^T u0), partials r1 = K v1
    {
        float4 p = make_float4(0,0,0,0);
        for (int j = gwid; j < VW; j += NWRP){
            float4 k = make_float4(0,0,0,0);
            if (lane < 25) k = ((const float4*)(g_KtwT + (size_t)j*KTOP))[lane];
            float t = warp_bfly(k.x + k.y + k.z + k.w) * invK;
            float v = g_b2[j] / (t + 1e-16f);
            if (lane == 0) g_v2[j] = v;
            p.x += k.x*v; p.y += k.y*v; p.z += k.z*v; p.w += k.w*v;
        }
        if (lane < 25){
            spw[w][4*lane] = p.x; spw[w][4*lane+1] = p.y;
            spw[w][4*lane+2] = p.z; spw[w][4*lane+3] = p.w;
        }
    }
    __syncthreads();
    if (tid < 100){
        float s = 0.f;
#pragma unroll
        for (int x = 0; x < 8; x++) s += spw[x][tid];
        g_part2[0][cta*128 + tid] = s;
    }
    gbar(&g_bc2, &g_bg2, NC2);

    float err = 1.0f; int cpt = 0, buf = 1;
    while (err > 0.005f && cpt < 5000){
        if (tid < 200){
            int col = (tid < 100) ? tid : (tid - 100);
            int lo = (tid < 100) ? 0 : (NC2/2), hi = (tid < 100) ? (NC2/2) : NC2;
            float s = 0.f;
            const float* pp = g_part2[buf ^ 1];
            for (int cc = lo; cc < hi; cc++) s += pp[cc*128 + col];
            r2[tid] = s;
        }
        __syncthreads();
        if (tid < 128) u_sm[tid] = (tid < 100) ? (invK / (r2[tid] + r2[tid+100] + 1e-16f)) : 0.f;
        __syncthreads();
        cpt++;
        bool check = (cpt % 50) == 1;
        float4 uu = (lane < 25) ? ((const float4*)u_sm)[lane] : make_float4(0,0,0,0);
        float4 p = make_float4(0,0,0,0);
        float ep = 0.f;
        for (int j = gwid; j < VW; j += 2*NWRP){
            int j2 = j + NWRP;
            float4 ka = make_float4(0,0,0,0), kb = make_float4(0,0,0,0);
            if (lane < 25){
                ka = ((const float4*)(g_KtwT + (size_t)j*KTOP))[lane];
                if (j2 < VW) kb = ((const float4*)(g_KtwT + (size_t)j2*KTOP))[lane];
            }
            float ta = ka.x*uu.x + ka.y*uu.y + ka.z*uu.z + ka.w*uu.w;
            float tb = kb.x*uu.x + kb.y*uu.y + kb.z*uu.z + kb.w*uu.w;
            ta = warp_bfly(ta); tb = warp_bfly(tb);
            float bja = g_b2[j];
            float vna = bja / (ta + 1e-16f);
            if (lane == 0){
                float vo = g_v2[j];
                if (check) ep += fabsf(vo*ta - bja);
                g_v2fin[j] = vo;
                g_v2[j] = vna;
            }
            p.x += ka.x*vna; p.y += ka.y*vna; p.z += ka.z*vna; p.w += ka.w*vna;
            if (j2 < VW){
                float bjb = g_b2[j2];
                float vnb = bjb / (tb + 1e-16f);
                if (lane == 0){
                    float vo = g_v2[j2];
                    if (check) ep += fabsf(vo*tb - bjb);
                    g_v2fin[j2] = vo;
                    g_v2[j2] = vnb;
                }
                p.x += kb.x*vnb; p.y += kb.y*vnb; p.z += kb.z*vnb; p.w += kb.w*vnb;
            }
        }
        if (lane < 25){
            spw[w][4*lane] = p.x; spw[w][4*lane+1] = p.y;
            spw[w][4*lane+2] = p.z; spw[w][4*lane+3] = p.w;
        }
        if (check){
            red[tid] = ep; __syncthreads();
            for (int s2 = 128; s2 > 0; s2 >>= 1){ if (tid < s2) red[tid] += red[tid+s2]; __syncthreads(); }
            if (tid == 0) g_err2[cta] = red[0];
        }
        __syncthreads();
        if (tid < 100){
            float s = 0.f;
#pragma unroll
            for (int x = 0; x < 8; x++) s += spw[x][tid];
            g_part2[buf][cta*128 + tid] = s;
        }
        gbar(&g_bc2, &g_bg2, NC2);
        if (check){
            float e = (tid < NC2) ? g_err2[tid] : 0.f;
            red[tid] = e; __syncthreads();
            for (int s2 = 128; s2 > 0; s2 >>= 1){ if (tid < s2) red[tid] += red[tid+s2]; __syncthreads(); }
            err = red[0];
        }
        __syncthreads();
        buf ^= 1;
    }
    if (cta == 0 && tid < 100) g_u2[tid] = u_sm[tid];
}

__global__ __launch_bounds__(256) void sink_fused(){
    if (blockIdx.x < NC1) sink_dt(blockIdx.x);
    else                  sink_tw(blockIdx.x - NC1);
}

// ---------------- fused theta+beta (bf16 padded) + transport losses ----------
__global__ __launch_bounds__(256) void tb_kernel(){
    __shared__ float red[256];
    int tid = threadIdx.x, b = blockIdx.x;
    float part = 0.f;
    if (b < 128){
        for (int idx = b*256 + tid; idx < NDOC*128; idx += 128*256){
            int i = idx >> 7, k = idx & 127;
            float o = 0.f;
            if (k < KTOP){
                float tr = g_u1[i] * g_Kdt[(size_t)i*KTOP + k] * g_v1fin[k];
                o = tr * (float)NDOC;
                part += tr * g_Mdt[(size_t)i*KTOP + k];
            }
            g_thetaB[idx] = __float2bfloat16(o);
        }
    } else {
        int bb = b - 128;
        for (int idx = bb*256 + tid; idx < VWP*128; idx += 384*256){
            int j = idx >> 7, k = idx & 127;
            float o = 0.f;
            if (j < VW && k < KTOP){
                float tr = g_u2[k] * g_KtwT[(size_t)j*KTOP + k] * g_v2fin[j];
                o = tr * (float)KTOP;
                part += tr * g_MtwT[(size_t)j*KTOP + k];
            }
            g_betaB[idx] = __float2bfloat16(o);
        }
    }
    red[tid] = part; __syncthreads();
    for (int s = 128; s > 0; s >>= 1){ if (tid < s) red[tid] += red[tid+s]; __syncthreads(); }
    if (tid == 0) atomicAdd(&g_acc[(b < 128) ? 0 : 1], (double)red[0]);
}

// ---------------- tensor-core recon GEMM + log-loss --------------------------
// CTA 128x64, 8 warps (4x2) of 32x32, mma.sync m16n8k16 bf16, K=128 in 2 chunks.
// bow epilogue operands prefetched into registers before the mainloop.
__global__ __launch_bounds__(256, 2) void recon_kernel(const float* __restrict__ bow){
    __shared__ __nv_bfloat16 As[128*72];
    __shared__ __nv_bfloat16 Bs[64*72];
    __shared__ float red[256];
    int tid = threadIdx.x, lane = tid & 31, w = tid >> 5;
    int wr = w >> 1, wc = w & 1;
    int g = lane >> 2, c = lane & 3;
    int r0 = blockIdx.y * 128, c0 = blockIdx.x * 64;

    // prefetch bow: [mi][ni][half] float2
    float2 bwreg[2][4][2];
#pragma unroll
    for (int mi = 0; mi < 2; mi++){
        int R = r0 + wr*32 + mi*16 + g;
#pragma unroll
        for (int ni = 0; ni < 4; ni++){
            int C = c0 + wc*32 + ni*8 + c*2;
            if (C < VW){
                bwreg[mi][ni][0] = *(const float2*)&bow[(size_t)R*VW + C];
                bwreg[mi][ni][1] = *(const float2*)&bow[(size_t)(R + 8)*VW + C];
            } else {
                bwreg[mi][ni][0] = make_float2(0.f, 0.f);
                bwreg[mi][ni][1] = make_float2(0.f, 0.f);
            }
        }
    }

    float acc[2][4][4];
#pragma unroll
    for (int mi = 0; mi < 2; mi++)
#pragma unroll
        for (int ni = 0; ni < 4; ni++)
#pragma unroll
            for (int q = 0; q < 4; q++) acc[mi][ni][q] = 0.f;

    const uint32_t* Aw = (const uint32_t*)As;
    const uint32_t* Bw = (const uint32_t*)Bs;
    int rabase = (wr*32 + g)*36;
    int rbbase = (wc*32 + g)*36;

    for (int chunk = 0; chunk < 2; chunk++){
        __syncthreads();
        for (int f = tid; f < 1024; f += 256){
            int r = f >> 3, q = f & 7;
            uint4 val = *(const uint4*)&g_thetaB[(size_t)(r0 + r)*128 + chunk*64 + q*8];
            *(uint4*)&As[r*72 + q*8] = val;
        }
        for (int f = tid; f < 512; f += 256){
            int r = f >> 3, q = f & 7;
            uint4 val = *(const uint4*)&g_betaB[(size_t)(c0 + r)*128 + chunk*64 + q*8];
            *(uint4*)&Bs[r*72 + q*8] = val;
        }
        __syncthreads();
#pragma unroll
        for (int ks = 0; ks < 4; ks++){
            int ka = ks*8 + c;
            uint32_t a0[2], a1[2], a2[2], a3[2], b0[4], b1[4];
#pragma unroll
            for (int mi = 0; mi < 2; mi++){
                int base = rabase + mi*16*36 + ka;
                a0[mi] = Aw[base]; a1[mi] = Aw[base + 8*36];
                a2[mi] = Aw[base + 4]; a3[mi] = Aw[base + 8*36 + 4];
            }
#pragma unroll
            for (int ni = 0; ni < 4; ni++){
                int base = rbbase + ni*8*36 + ka;
                b0[ni] = Bw[base]; b1[ni] = Bw[base + 4];
            }
#pragma unroll
            for (int mi = 0; mi < 2; mi++)
#pragma unroll
                for (int ni = 0; ni < 4; ni++){
                    asm volatile(
                        "mma.sync.aligned.m16n8k16.row.col.f32.bf16.bf16.f32 "
                        "{%0,%1,%2,%3}, {%4,%5,%6,%7}, {%8,%9}, {%0,%1,%2,%3};"
                        : "+f"(acc[mi][ni][0]), "+f"(acc[mi][ni][1]),
                          "+f"(acc[mi][ni][2]), "+f"(acc[mi][ni][3])
                        : "r"(a0[mi]), "r"(a1[mi]), "r"(a2[mi]), "r"(a3[mi]),
                          "r"(b0[ni]), "r"(b1[ni]));
                }
        }
    }

    float part = 0.f;
#pragma unroll
    for (int mi = 0; mi < 2; mi++)
#pragma unroll
        for (int ni = 0; ni < 4; ni++){
            part += bwreg[mi][ni][0].x * __logf(acc[mi][ni][0] + 1e-12f)
                  + bwreg[mi][ni][0].y * __logf(acc[mi][ni][1] + 1e-12f)
                  + bwreg[mi][ni][1].x * __logf(acc[mi][ni][2] + 1e-12f)
                  + bwreg[mi][ni][1].y * __logf(acc[mi][ni][3] + 1e-12f);
        }
    red[tid] = part; __syncthreads();
    for (int s = 128; s > 0; s >>= 1){ if (tid < s) red[tid] += red[tid+s]; __syncthreads(); }
    if (tid == 0) atomicAdd(&g_acc[2], (double)red[0]);
}

__global__ void final_kernel(float* out){
    out[0] = (float)(g_acc[0] + g_acc[1] - g_acc[2] * (1.0 / (double)NDOC));
}

// ---------------- launch -----------------------------------------------------
extern "C" void kernel_launch(void* const* d_in, const int* in_sizes, int n_in,
                              void* d_out, int out_size)
{
    const float *bow = nullptr, *doc = nullptr, *word = nullptr,
                *topic = nullptr, *ww = nullptr, *tw = nullptr;
    for (int i = 0; i < n_in; i++){
        const float* p = (const float*)d_in[i];
        switch (in_sizes[i]){
            case 40960000: bow = p;   break;
            case 1572864:  doc = p;   break;
            case 3840000:  word = p;  break;
            case 38400:    topic = p; break;
            case 10000:    ww = p;    break;
            case 100:      tw = p;    break;
        }
    }
    float* out = (float*)d_out;

    prologue_kernel<<<151, 256>>>(doc, topic, word, tw, ww);
    dist_mma<<<32 + 79, 256>>>(doc, word, topic);
    sink_fused<<<NC1 + NC2, 256>>>();
    tb_kernel<<<512, 256>>>();
    recon_kernel<<<dim3(157, 32), 256>>>(bow);
    final_kernel<<<1, 1>>>(out);
}